// round 17
// baseline (speedup 1.0000x reference)
#include <cuda_runtime.h>
#include <cstdint>

// DepthwiseStencil3D, variant v9: R9 schedule + single 32KB TMA bulk store.
// out flat channel ch = c*6+k is x[c] shifted by tap k, zero-padded.
// Taps: 0 -> w+1, 1 -> w-1, 2 -> h+1, 3 -> h-1, 4 -> d+1, 5 -> d-1.
//
// Each 256-thread CTA owns one contiguous 8192-element (32 KB) region of ONE
// output channel (channel-major grid = linear write sweep, measured optimum).
// The region is computed into SMEM then emitted as ONE cp.async.bulk 32 KB
// shared->global burst. Loads: 256-bit L2 evict_last.

#define C_ 16
#define D_ 128
#define H_ 128
#define W_ 128
#define HW_ (H_ * W_)          // 16384
#define DHW_ (D_ * HW_)        // 2097152
#define REG_ELEMS 8192
#define REG_BYTES (REG_ELEMS * 4)   // 32768

struct V8 { uint32_t r[8]; };

__device__ __forceinline__ V8 ldg_v8_el(const float* p) {
    V8 v;
    asm volatile(
        "{ .reg .b64 pol;\n"
        "  createpolicy.fractional.L2::evict_last.b64 pol, 1.0;\n"
        "  ld.global.L2::cache_hint.v8.b32 {%0,%1,%2,%3,%4,%5,%6,%7}, [%8], pol; }\n"
        : "=r"(v.r[0]), "=r"(v.r[1]), "=r"(v.r[2]), "=r"(v.r[3]),
          "=r"(v.r[4]), "=r"(v.r[5]), "=r"(v.r[6]), "=r"(v.r[7])
        : "l"(p));
    return v;
}

__device__ __forceinline__ void sts_v8(float* dst, const V8& v) {
    uint4* d = reinterpret_cast<uint4*>(dst);
    d[0] = make_uint4(v.r[0], v.r[1], v.r[2], v.r[3]);
    d[1] = make_uint4(v.r[4], v.r[5], v.r[6], v.r[7]);
}

__device__ __forceinline__ uint32_t smem_u32(const void* p) {
    uint32_t a;
    asm("{ .reg .u64 t; cvta.to.shared.u64 t, %1; cvt.u32.u64 %0, t; }"
        : "=r"(a) : "l"(p));
    return a;
}

__global__ void __launch_bounds__(256) stencil6_kernel(
    const float* __restrict__ x, float* __restrict__ out)
{
    __shared__ float sbuf[REG_ELEMS];    // 32 KB staging buffer

    int t   = threadIdx.x;
    int bid = blockIdx.x;

    int ch  = bid >> 8;           // output channel 0..95 (channel-major)
    int reg = bid & 255;          // 8192-element region within channel
    int c   = ch / 6;
    int k   = ch - 6 * c;         // tap kind, uniform per CTA

    const float* __restrict__ xc = x + c * DHW_;

    int loff0 = t << 3;                       // offset within the region
    int off0  = (reg << 13) + loff0;          // within-channel offset

    V8 zero;
#pragma unroll
    for (int i = 0; i < 8; i++) zero.r[i] = 0u;

    if (k < 2) {
        // w-shift taps: aligned load + lane shuffle for the edge scalar.
        unsigned full = 0xffffffffu;
        int w8 = t & 15;          // 8-float chunk index within the W row
#pragma unroll
        for (int i = 0; i < 4; i++) {
            V8 v = ldg_v8_el(xc + off0 + (i << 11));
            V8 r;
            if (k == 0) {         // w+1
                uint32_t xr = __shfl_down_sync(full, v.r[0], 1);
                if (w8 == 15) xr = 0u;
#pragma unroll
                for (int j = 0; j < 7; j++) r.r[j] = v.r[j + 1];
                r.r[7] = xr;
            } else {              // w-1
                uint32_t xl = __shfl_up_sync(full, v.r[7], 1);
                if (w8 == 0) xl = 0u;
                r.r[0] = xl;
#pragma unroll
                for (int j = 1; j < 8; j++) r.r[j] = v.r[j - 1];
            }
            sts_v8(&sbuf[loff0 + (i << 11)], r);
        }
    } else {
        // h/d-shift taps: pure shifted copies with zero padding at the edge.
        int delta = (k == 2) ?  W_  :
                    (k == 3) ? -W_  :
                    (k == 4) ?  HW_ : -HW_;
#pragma unroll
        for (int i = 0; i < 4; i++) {
            int o = off0 + (i << 11);
            bool ok;
            if      (k == 2) ok = ((o >> 7) & 127) < H_ - 1;  // h < 127
            else if (k == 3) ok = ((o >> 7) & 127) > 0;       // h > 0
            else if (k == 4) ok = (o >> 14) < D_ - 1;         // d < 127
            else             ok = (o >> 14) > 0;              // d > 0
            V8 r = ok ? ldg_v8_el(xc + o + delta) : zero;
            sts_v8(&sbuf[loff0 + (i << 11)], r);
        }
    }

    __syncthreads();

    // Single 32 KB bulk shared->global burst for the whole region.
    if (t == 0) {
        asm volatile("fence.proxy.async.shared::cta;" ::: "memory");
        float* gdst = out + ch * DHW_ + (reg << 13);
        uint32_t saddr = smem_u32(&sbuf[0]);
        asm volatile(
            "cp.async.bulk.global.shared::cta.bulk_group [%0], [%1], %2;"
            :: "l"(gdst), "r"(saddr), "n"(REG_BYTES) : "memory");
        asm volatile("cp.async.bulk.commit_group;" ::: "memory");
        asm volatile("cp.async.bulk.wait_group 0;" ::: "memory");
    }
}

extern "C" void kernel_launch(void* const* d_in, const int* in_sizes, int n_in,
                              void* d_out, int out_size)
{
    const float* x = (const float*)d_in[0];
    float* out = (float*)d_out;

    // 96 channels * 256 regions = 24576 CTAs; each emits one 32 KB TMA burst.
    stencil6_kernel<<<24576, 256>>>(x, out);
}